// round 1
// baseline (speedup 1.0000x reference)
#include <cuda_runtime.h>

// Problem constants (fixed shapes from reference setup_inputs)
static constexpr int B = 8;
static constexpr int T = 2048;
static constexpr int D = 512;   // x feature dim
static constexpr int K = 3;     // kernel size, pad = 1
static constexpr int F = 512;   // filters
static constexpr int BT = B * T;          // 16384 rows
static constexpr int F4 = F / 4;          // 128 float4 per (b,t) output row

// Scratch for row sums s[b,t] = sum_d x[b,t,d]. Static device global (no allocation).
__device__ float g_s[BT];

// Kernel 1: per-row sum of x. One warp per row, 8 warps (256 threads) per block.
// Each lane reads 4 float4s (16 floats), then warp shuffle-reduce.
__global__ void __launch_bounds__(256) rowsum_kernel(const float* __restrict__ x) {
    const int warp_in_block = threadIdx.x >> 5;
    const int lane = threadIdx.x & 31;
    const int row = blockIdx.x * 8 + warp_in_block;   // grid sized exactly: BT/8 blocks

    const float4* __restrict__ xr =
        reinterpret_cast<const float4*>(x + (size_t)row * D);

    float acc = 0.0f;
#pragma unroll
    for (int i = 0; i < 4; ++i) {
        float4 v = xr[lane + 32 * i];
        acc += (v.x + v.y) + (v.z + v.w);
    }
#pragma unroll
    for (int o = 16; o > 0; o >>= 1)
        acc += __shfl_xor_sync(0xffffffffu, acc, o);

    if (lane == 0)
        g_s[row] = acc;
}

// Kernel 2: out[b,t,f] = s[bt-1]*ker[bt,0,f] + s[bt]*ker[bt,1,f] + s[bt+1]*ker[bt,2,f]
// (with zero padding at t==0 / t==T-1). One thread per output float4.
__global__ void __launch_bounds__(256) combine_kernel(const float* __restrict__ ker,
                                                      float* __restrict__ out) {
    const int idx = blockIdx.x * blockDim.x + threadIdx.x;   // float4 index, exact grid
    const int f4 = idx & (F4 - 1);
    const int bt = idx >> 7;                                  // F4 = 128 = 2^7
    const int t  = bt & (T - 1);                              // T = 2048 = 2^11

    const float sp = (t > 0)     ? g_s[bt - 1] : 0.0f;
    const float sc =               g_s[bt];
    const float sn = (t < T - 1) ? g_s[bt + 1] : 0.0f;

    const float4* __restrict__ kb =
        reinterpret_cast<const float4*>(ker + (size_t)bt * (K * F));
    // k-planes are contiguous: [bt][0][0..F), [bt][1][0..F), [bt][2][0..F)
    float4 a = kb[f4];                 // k = 0
    float4 b = kb[f4 + F4];           // k = 1
    float4 c = kb[f4 + 2 * F4];       // k = 2

    float4 o;
    o.x = fmaf(sp, a.x, fmaf(sc, b.x, sn * c.x));
    o.y = fmaf(sp, a.y, fmaf(sc, b.y, sn * c.y));
    o.z = fmaf(sp, a.z, fmaf(sc, b.z, sn * c.z));
    o.w = fmaf(sp, a.w, fmaf(sc, b.w, sn * c.w));

    reinterpret_cast<float4*>(out)[idx] = o;
}

extern "C" void kernel_launch(void* const* d_in, const int* in_sizes, int n_in,
                              void* d_out, int out_size) {
    const float* x   = (const float*)d_in[0];   // [B, T, D]
    const float* ker = (const float*)d_in[1];   // [B, T, K, F]
    float* out = (float*)d_out;                 // [B, T, F]

    (void)in_sizes; (void)n_in; (void)out_size;

    // Kernel 1: BT rows, 8 rows/block
    rowsum_kernel<<<BT / 8, 256>>>(x);

    // Kernel 2: BT * F4 float4 outputs, 256 threads/block (exact division)
    const int total4 = BT * F4;                 // 2,097,152
    combine_kernel<<<total4 / 256, 256>>>(ker, out);
}

// round 2
// speedup vs baseline: 1.0250x; 1.0250x over previous
#include <cuda_runtime.h>

// Fixed problem shapes
static constexpr int B  = 8;
static constexpr int T  = 2048;
static constexpr int D  = 512;    // x feature dim
static constexpr int K  = 3;      // kernel size, pad = 1
static constexpr int F  = 512;    // filters
static constexpr int BT = B * T;  // 16384 rows
static constexpr int F4 = F / 4;  // 128 float4 per row
static constexpr int D4 = D / 4;  // 128 float4 per x row

static constexpr int TT = 16;     // t-rows per block (divides T)

// Fused kernel:
//   phase 1: compute s[r] = sum_d x[bt0-1+r, d] for r in [0, TT+2) into smem
//            (zero outside the batch's [0,T) range)
//   phase 2: out[bt0+r, f] = s[r]*ker[bt0+r,0,f] + s[r+1]*ker[bt0+r,1,f]
//                          + s[r+2]*ker[bt0+r,2,f]
__global__ void __launch_bounds__(256) fused_dynconv_kernel(
    const float* __restrict__ x,
    const float* __restrict__ ker,
    float* __restrict__ out)
{
    __shared__ float s_s[TT + 2];

    const int bt0 = blockIdx.x * TT;          // first global row of this tile
    const int t0  = bt0 & (T - 1);            // t of first row (T = 2048 pow2)
    const int warp = threadIdx.x >> 5;
    const int lane = threadIdx.x & 31;

    // ---- Phase 1: row sums for rows bt0-1 .. bt0+TT (TT+2 = 18 rows) ----
    // 8 warps, each takes rows r = warp, warp+8, warp+16.
    for (int r = warp; r < TT + 2; r += 8) {
        const int tg = t0 - 1 + r;            // t within this batch
        float acc = 0.0f;
        if (tg >= 0 && tg < T) {
            const float4* __restrict__ xr =
                reinterpret_cast<const float4*>(x + (size_t)(bt0 - 1 + r) * D);
#pragma unroll
            for (int i = 0; i < D4 / 32; ++i) {   // 4 float4 per lane
                float4 v = xr[lane + 32 * i];
                acc += (v.x + v.y) + (v.z + v.w);
            }
#pragma unroll
            for (int o = 16; o > 0; o >>= 1)
                acc += __shfl_xor_sync(0xffffffffu, acc, o);
        }
        if (lane == 0)
            s_s[r] = acc;
    }
    __syncthreads();

    // ---- Phase 2: combine. TT*F4 = 2048 float4 outputs, 256 threads -> 8 iters.
    const float4* __restrict__ kb =
        reinterpret_cast<const float4*>(ker + (size_t)bt0 * (K * F));
    float4* __restrict__ ob =
        reinterpret_cast<float4*>(out + (size_t)bt0 * F);

#pragma unroll
    for (int it = 0; it < (TT * F4) / 256; ++it) {
        const int idx = it * 256 + threadIdx.x;
        const int r   = idx >> 7;             // F4 = 128
        const int f4  = idx & (F4 - 1);

        const float sp = s_s[r];
        const float sc = s_s[r + 1];
        const float sn = s_s[r + 2];

        const float4* kr = kb + (size_t)r * (K * F4);
        float4 a = kr[f4];              // k = 0
        float4 b = kr[f4 + F4];        // k = 1
        float4 c = kr[f4 + 2 * F4];    // k = 2

        float4 o;
        o.x = fmaf(sp, a.x, fmaf(sc, b.x, sn * c.x));
        o.y = fmaf(sp, a.y, fmaf(sc, b.y, sn * c.y));
        o.z = fmaf(sp, a.z, fmaf(sc, b.z, sn * c.z));
        o.w = fmaf(sp, a.w, fmaf(sc, b.w, sn * c.w));
        ob[idx] = o;
    }
}

extern "C" void kernel_launch(void* const* d_in, const int* in_sizes, int n_in,
                              void* d_out, int out_size) {
    const float* x   = (const float*)d_in[0];   // [B, T, D]
    const float* ker = (const float*)d_in[1];   // [B, T, K, F]
    float* out = (float*)d_out;                 // [B, T, F]
    (void)in_sizes; (void)n_in; (void)out_size;

    fused_dynconv_kernel<<<BT / TT, 256>>>(x, ker, out);
}

// round 3
// speedup vs baseline: 1.2779x; 1.2468x over previous
#include <cuda_runtime.h>

// Fixed problem shapes
static constexpr int B  = 8;
static constexpr int T  = 2048;
static constexpr int D  = 512;    // x feature dim
static constexpr int K  = 3;      // kernel size, pad = 1
static constexpr int F  = 512;    // filters
static constexpr int BT = B * T;  // 16384 rows
static constexpr int F4 = F / 4;  // 128 float4 per row
static constexpr int D4 = D / 4;  // 128 float4 per x row

static constexpr int TT = 16;     // t-rows per block (divides T)

// Fused kernel:
//   phase 1: s[r] = sum_d x[bt0-1+r, d] for r in [0, TT+2) into smem
//   phase 2: out[bt0+r, f] = s[r]*ker[.,0,f] + s[r+1]*ker[.,1,f] + s[r+2]*ker[.,2,f]
// kernels-loads and out-stores are streaming (no reuse); x keeps default caching
// so the 2-row halo shared with neighbor blocks stays L2-resident.
__global__ void __launch_bounds__(256, 6) fused_dynconv_kernel(
    const float* __restrict__ x,
    const float* __restrict__ ker,
    float* __restrict__ out)
{
    __shared__ float s_s[TT + 2];

    const int bt0 = blockIdx.x * TT;          // first global row of this tile
    const int t0  = bt0 & (T - 1);            // t of first row (T = 2048 pow2)
    const int warp = threadIdx.x >> 5;
    const int lane = threadIdx.x & 31;

    // ---- Phase 1: row sums for rows bt0-1 .. bt0+TT (18 rows, 8 warps) ----
    for (int r = warp; r < TT + 2; r += 8) {
        const int tg = t0 - 1 + r;            // t within this batch
        float acc = 0.0f;
        if (tg >= 0 && tg < T) {
            const float4* __restrict__ xr =
                reinterpret_cast<const float4*>(x + (size_t)(bt0 - 1 + r) * D);
            float4 v0 = xr[lane];
            float4 v1 = xr[lane + 32];
            float4 v2 = xr[lane + 64];
            float4 v3 = xr[lane + 96];
            acc = ((v0.x + v0.y) + (v0.z + v0.w))
                + ((v1.x + v1.y) + (v1.z + v1.w))
                + ((v2.x + v2.y) + (v2.z + v2.w))
                + ((v3.x + v3.y) + (v3.z + v3.w));
#pragma unroll
            for (int o = 16; o > 0; o >>= 1)
                acc += __shfl_xor_sync(0xffffffffu, acc, o);
        }
        if (lane == 0)
            s_s[r] = acc;
    }
    __syncthreads();

    // ---- Phase 2: combine. TT*F4 = 2048 float4 outputs, 256 threads, 8 iters.
    const float4* __restrict__ kb =
        reinterpret_cast<const float4*>(ker + (size_t)bt0 * (K * F));
    float4* __restrict__ ob =
        reinterpret_cast<float4*>(out + (size_t)bt0 * F);

#pragma unroll
    for (int it = 0; it < (TT * F4) / 256; ++it) {
        const int idx = it * 256 + threadIdx.x;
        const int r   = idx >> 7;             // F4 = 128
        const int f4  = idx & (F4 - 1);

        const float sp = s_s[r];
        const float sc = s_s[r + 1];
        const float sn = s_s[r + 2];

        const float4* kr = kb + (size_t)r * (K * F4);
        float4 a = __ldcs(kr + f4);            // k = 0, streaming
        float4 b = __ldcs(kr + f4 + F4);       // k = 1
        float4 c = __ldcs(kr + f4 + 2 * F4);   // k = 2

        float4 o;
        o.x = fmaf(sp, a.x, fmaf(sc, b.x, sn * c.x));
        o.y = fmaf(sp, a.y, fmaf(sc, b.y, sn * c.y));
        o.z = fmaf(sp, a.z, fmaf(sc, b.z, sn * c.z));
        o.w = fmaf(sp, a.w, fmaf(sc, b.w, sn * c.w));
        __stcs(ob + idx, o);                   // streaming store
    }
}

extern "C" void kernel_launch(void* const* d_in, const int* in_sizes, int n_in,
                              void* d_out, int out_size) {
    const float* x   = (const float*)d_in[0];   // [B, T, D]
    const float* ker = (const float*)d_in[1];   // [B, T, K, F]
    float* out = (float*)d_out;                 // [B, T, F]
    (void)in_sizes; (void)n_in; (void)out_size;

    fused_dynconv_kernel<<<BT / TT, 256>>>(x, ker, out);
}

// round 4
// speedup vs baseline: 1.3667x; 1.0694x over previous
#include <cuda_runtime.h>

// Fixed problem shapes
static constexpr int B  = 8;
static constexpr int T  = 2048;
static constexpr int D  = 512;    // x feature dim
static constexpr int K  = 3;      // kernel size, pad = 1
static constexpr int F  = 512;    // filters
static constexpr int BT = B * T;  // 16384 rows
static constexpr int F4 = F / 4;  // 128 float4 per row

static constexpr int TT = 16;     // t-rows per block (divides T)
static constexpr int ITERS = (TT * F4) / 256;   // 8

__global__ void __launch_bounds__(256, 4) fused_dynconv_kernel(
    const float* __restrict__ x,
    const float* __restrict__ ker,
    float* __restrict__ out)
{
    __shared__ float s_s[TT + 2];

    const int bt0 = blockIdx.x * TT;
    const int t0  = bt0 & (T - 1);            // T = 2048, power of 2
    const int warp = threadIdx.x >> 5;
    const int lane = threadIdx.x & 31;

    const float4* __restrict__ kb =
        reinterpret_cast<const float4*>(ker + (size_t)bt0 * (K * F));
    float4* __restrict__ ob =
        reinterpret_cast<float4*>(out + (size_t)bt0 * F);

    // ---- Prefetch kernels-loads for iterations 0 and 1 BEFORE the barrier.
    // These are independent of the row sums; issuing them here keeps the
    // memory pipe full while phase 1 + BAR resolve.
    const int idx0 = threadIdx.x;            // iter 0
    const int idx1 = 256 + threadIdx.x;      // iter 1
    const int r0 = idx0 >> 7, f40 = idx0 & (F4 - 1);
    const int r1 = idx1 >> 7, f41 = idx1 & (F4 - 1);
    const float4* kr0 = kb + (size_t)r0 * (K * F4);
    const float4* kr1 = kb + (size_t)r1 * (K * F4);
    float4 pa0 = __ldcs(kr0 + f40);
    float4 pb0 = __ldcs(kr0 + f40 + F4);
    float4 pc0 = __ldcs(kr0 + f40 + 2 * F4);
    float4 pa1 = __ldcs(kr1 + f41);
    float4 pb1 = __ldcs(kr1 + f41 + F4);
    float4 pc1 = __ldcs(kr1 + f41 + 2 * F4);

    // ---- Phase 1: row sums for rows bt0-1 .. bt0+TT (18 rows, 8 warps) ----
    for (int r = warp; r < TT + 2; r += 8) {
        const int tg = t0 - 1 + r;
        float acc = 0.0f;
        if (tg >= 0 && tg < T) {
            const float4* __restrict__ xr =
                reinterpret_cast<const float4*>(x + (size_t)(bt0 - 1 + r) * D);
            float4 v0 = xr[lane];
            float4 v1 = xr[lane + 32];
            float4 v2 = xr[lane + 64];
            float4 v3 = xr[lane + 96];
            acc = ((v0.x + v0.y) + (v0.z + v0.w))
                + ((v1.x + v1.y) + (v1.z + v1.w))
                + ((v2.x + v2.y) + (v2.z + v2.w))
                + ((v3.x + v3.y) + (v3.z + v3.w));
#pragma unroll
            for (int o = 16; o > 0; o >>= 1)
                acc += __shfl_xor_sync(0xffffffffu, acc, o);
        }
        if (lane == 0)
            s_s[r] = acc;
    }
    __syncthreads();

    // ---- Phase 2: depth-2 software-pipelined combine ----
#pragma unroll
    for (int it = 0; it < ITERS; ++it) {
        // Prefetch iteration it+2
        float4 na, nb, nc;
        if (it + 2 < ITERS) {
            const int idxn = (it + 2) * 256 + threadIdx.x;
            const int rn = idxn >> 7, f4n = idxn & (F4 - 1);
            const float4* krn = kb + (size_t)rn * (K * F4);
            na = __ldcs(krn + f4n);
            nb = __ldcs(krn + f4n + F4);
            nc = __ldcs(krn + f4n + 2 * F4);
        }

        // Compute iteration it from the depth-2 pipeline registers
        const int idx = it * 256 + threadIdx.x;
        const int r   = idx >> 7;
        const float sp = s_s[r];
        const float sc = s_s[r + 1];
        const float sn = s_s[r + 2];

        float4 o;
        o.x = fmaf(sp, pa0.x, fmaf(sc, pb0.x, sn * pc0.x));
        o.y = fmaf(sp, pa0.y, fmaf(sc, pb0.y, sn * pc0.y));
        o.z = fmaf(sp, pa0.z, fmaf(sc, pb0.z, sn * pc0.z));
        o.w = fmaf(sp, pa0.w, fmaf(sc, pb0.w, sn * pc0.w));
        __stcs(ob + idx, o);

        // Rotate pipeline registers
        pa0 = pa1; pb0 = pb1; pc0 = pc1;
        pa1 = na;  pb1 = nb;  pc1 = nc;
    }
}

extern "C" void kernel_launch(void* const* d_in, const int* in_sizes, int n_in,
                              void* d_out, int out_size) {
    const float* x   = (const float*)d_in[0];   // [B, T, D]
    const float* ker = (const float*)d_in[1];   // [B, T, K, F]
    float* out = (float*)d_out;                 // [B, T, F]
    (void)in_sizes; (void)n_in; (void)out_size;

    fused_dynconv_kernel<<<BT / TT, 256>>>(x, ker, out);
}